// round 8
// baseline (speedup 1.0000x reference)
#include <cuda_runtime.h>
#include <cuda_bf16.h>
#include <math.h>
#include <stdint.h>

#define Bsz 4
#define Nn 1024
#define Cc 512
#define Hh 8
#define DH 64
#define BH 32
#define INNER 512
#define Ff 160   // 64 (E) + 64 (S) + 32 (H)
#define LDA 132  // smem stride for 128-wide tiles
#define LDB 68   // smem stride for 64-wide tiles

typedef unsigned long long u64;

// ---- scratch (static device allocations; no runtime alloc) ----
__device__ float g_Q[BH * Nn * DH];
__device__ float g_K[BH * Nn * DH];
__device__ float g_V[BH * Nn * DH];
__device__ float g_FQ[BH * Nn * Ff];
__device__ float g_FK[BH * Nn * Ff];
__device__ float g_QA[BH * Nn];
__device__ float g_QU[BH * Nn];
__device__ float g_KB[BH * Nn];
__device__ float g_KV[BH * Nn];
__device__ float g_S[(size_t)BH * Nn * Nn];  // scores -> probs (128 MB)
__device__ float g_O[Bsz * Nn * INNER];

__device__ __forceinline__ float softplusf(float x) {
    return (x > 20.f) ? x : log1pf(expf(x));
}
__device__ __forceinline__ float fast_sqrt(float x) {
    float r; asm("sqrt.approx.f32 %0, %1;" : "=f"(r) : "f"(x)); return r;
}
__device__ __forceinline__ float fast_rcp(float x) {
    float r; asm("rcp.approx.f32 %0, %1;" : "=f"(r) : "f"(x)); return r;
}

// ---- packed f32x2 FMA ----
__device__ __forceinline__ void fma2(u64& d, u64 a, u64 b) {
    asm("fma.rn.f32x2 %0, %1, %2, %0;" : "+l"(d) : "l"(a), "l"(b));
}
__device__ __forceinline__ u64 pack2(float lo, float hi) {
    u64 r; asm("mov.b64 %0, {%1, %2};" : "=l"(r) : "f"(lo), "f"(hi)); return r;
}
__device__ __forceinline__ void unpack2(u64 v, float& lo, float& hi) {
    asm("mov.b64 {%0, %1}, %2;" : "=f"(lo), "=f"(hi) : "l"(v));
}

// 8x8 microtile: acc2[8][4] (row-major, packed col pairs)
#define MICRO8X8(ACC2, a0, a1, b0, b1) {                                      \
    u64 q0 = pack2(b0.x, b0.y), q1 = pack2(b0.z, b0.w);                       \
    u64 q2 = pack2(b1.x, b1.y), q3 = pack2(b1.z, b1.w);                       \
    u64 ar;                                                                   \
    ar = pack2(a0.x, a0.x); fma2(ACC2[0][0],ar,q0); fma2(ACC2[0][1],ar,q1); fma2(ACC2[0][2],ar,q2); fma2(ACC2[0][3],ar,q3); \
    ar = pack2(a0.y, a0.y); fma2(ACC2[1][0],ar,q0); fma2(ACC2[1][1],ar,q1); fma2(ACC2[1][2],ar,q2); fma2(ACC2[1][3],ar,q3); \
    ar = pack2(a0.z, a0.z); fma2(ACC2[2][0],ar,q0); fma2(ACC2[2][1],ar,q1); fma2(ACC2[2][2],ar,q2); fma2(ACC2[2][3],ar,q3); \
    ar = pack2(a0.w, a0.w); fma2(ACC2[3][0],ar,q0); fma2(ACC2[3][1],ar,q1); fma2(ACC2[3][2],ar,q2); fma2(ACC2[3][3],ar,q3); \
    ar = pack2(a1.x, a1.x); fma2(ACC2[4][0],ar,q0); fma2(ACC2[4][1],ar,q1); fma2(ACC2[4][2],ar,q2); fma2(ACC2[4][3],ar,q3); \
    ar = pack2(a1.y, a1.y); fma2(ACC2[5][0],ar,q0); fma2(ACC2[5][1],ar,q1); fma2(ACC2[5][2],ar,q2); fma2(ACC2[5][3],ar,q3); \
    ar = pack2(a1.z, a1.z); fma2(ACC2[6][0],ar,q0); fma2(ACC2[6][1],ar,q1); fma2(ACC2[6][2],ar,q2); fma2(ACC2[6][3],ar,q3); \
    ar = pack2(a1.w, a1.w); fma2(ACC2[7][0],ar,q0); fma2(ACC2[7][1],ar,q1); fma2(ACC2[7][2],ar,q2); fma2(ACC2[7][3],ar,q3); \
}

// 8x4 microtile: acc2[8][2]
#define MICRO8X4(ACC2, a0, a1, b) {                                           \
    u64 q0 = pack2(b.x, b.y), q1 = pack2(b.z, b.w);                           \
    u64 ar;                                                                   \
    ar = pack2(a0.x, a0.x); fma2(ACC2[0][0],ar,q0); fma2(ACC2[0][1],ar,q1);   \
    ar = pack2(a0.y, a0.y); fma2(ACC2[1][0],ar,q0); fma2(ACC2[1][1],ar,q1);   \
    ar = pack2(a0.z, a0.z); fma2(ACC2[2][0],ar,q0); fma2(ACC2[2][1],ar,q1);   \
    ar = pack2(a0.w, a0.w); fma2(ACC2[3][0],ar,q0); fma2(ACC2[3][1],ar,q1);   \
    ar = pack2(a1.x, a1.x); fma2(ACC2[4][0],ar,q0); fma2(ACC2[4][1],ar,q1);   \
    ar = pack2(a1.y, a1.y); fma2(ACC2[5][0],ar,q0); fma2(ACC2[5][1],ar,q1);   \
    ar = pack2(a1.z, a1.z); fma2(ACC2[6][0],ar,q0); fma2(ACC2[6][1],ar,q1);   \
    ar = pack2(a1.w, a1.w); fma2(ACC2[7][0],ar,q0); fma2(ACC2[7][1],ar,q1);   \
}

// ============================================================
// K1: qkv = x @ w_qkv^T -> per-head Q/K/V. 128x128 tile, 8x8 micro.
// ============================================================
__global__ __launch_bounds__(256) void k_qkv(const float* __restrict__ x,
                                             const float* __restrict__ w) {
    __shared__ float As[2][16][LDA];
    __shared__ float Bs[2][16][LDA];
    int tid = threadIdx.x;
    int ty = tid >> 4, tx = tid & 15;
    int srow = tid >> 1, sq = (tid & 1) * 2;   // staging: row 0..127, k-quarter 0 or 2
    const float* Ap = x + ((size_t)(blockIdx.y * 128) + srow) * Cc + sq * 4;
    const float* Bp = w + ((size_t)(blockIdx.x * 128) + srow) * Cc + sq * 4;
    u64 acc2[8][4] = {};
    float4 a0v, a1v, b0v, b1v;

#define Q_LDG(KT) \
    a0v = *(const float4*)(Ap + (KT) * 16);     a1v = *(const float4*)(Ap + (KT) * 16 + 4); \
    b0v = *(const float4*)(Bp + (KT) * 16);     b1v = *(const float4*)(Bp + (KT) * 16 + 4);
#define Q_STS(BUF) \
    As[BUF][sq*4+0][srow]=a0v.x; As[BUF][sq*4+1][srow]=a0v.y; As[BUF][sq*4+2][srow]=a0v.z; As[BUF][sq*4+3][srow]=a0v.w; \
    As[BUF][sq*4+4][srow]=a1v.x; As[BUF][sq*4+5][srow]=a1v.y; As[BUF][sq*4+6][srow]=a1v.z; As[BUF][sq*4+7][srow]=a1v.w; \
    Bs[BUF][sq*4+0][srow]=b0v.x; Bs[BUF][sq*4+1][srow]=b0v.y; Bs[BUF][sq*4+2][srow]=b0v.z; Bs[BUF][sq*4+3][srow]=b0v.w; \
    Bs[BUF][sq*4+4][srow]=b1v.x; Bs[BUF][sq*4+5][srow]=b1v.y; Bs[BUF][sq*4+6][srow]=b1v.z; Bs[BUF][sq*4+7][srow]=b1v.w;
#define Q_COMP(BUF) \
    _Pragma("unroll") \
    for (int kk = 0; kk < 16; kk++) { \
        float4 a0 = *(const float4*)&As[BUF][kk][ty * 8]; \
        float4 a1 = *(const float4*)&As[BUF][kk][ty * 8 + 4]; \
        float4 b0 = *(const float4*)&Bs[BUF][kk][tx * 8]; \
        float4 b1 = *(const float4*)&Bs[BUF][kk][tx * 8 + 4]; \
        MICRO8X8(acc2, a0, a1, b0, b1) \
    }

    Q_LDG(0) Q_STS(0)
    __syncthreads();
    for (int kt = 0; kt < 32; kt += 2) {
        if (kt + 1 < 32) { Q_LDG(kt + 1) }
        Q_COMP(0)
        if (kt + 1 < 32) { Q_STS(1) }
        __syncthreads();
        if (kt + 1 < 32) {
            if (kt + 2 < 32) { Q_LDG(kt + 2) }
            Q_COMP(1)
            if (kt + 2 < 32) { Q_STS(0) }
            __syncthreads();
        }
    }

    float acc[8][8];
#pragma unroll
    for (int i = 0; i < 8; i++)
#pragma unroll
        for (int p = 0; p < 4; p++) unpack2(acc2[i][p], acc[i][2 * p], acc[i][2 * p + 1]);

    int m0 = blockIdx.y * 128 + ty * 8;
    int n0 = blockIdx.x * 128 + tx * 8;
#pragma unroll
    for (int i = 0; i < 8; i++) {
        int m = m0 + i;
        int b = m / Nn, n = m % Nn;
#pragma unroll
        for (int j = 0; j < 8; j++) {
            int jc = n0 + j;
            int part = jc / INNER, r = jc % INNER;
            int h = r / DH, d = r % DH;
            float* dst = (part == 0) ? g_Q : ((part == 1) ? g_K : g_V);
            dst[((size_t)(b * Hh + h) * Nn + n) * DH + d] = acc[i][j];
        }
    }
}

// ============================================================
// K2: per-token metric embeddings (unchanged)
// ============================================================
__global__ __launch_bounds__(256) void k_embed(const float* __restrict__ we, const float* __restrict__ be,
                                               const float* __restrict__ ws, const float* __restrict__ bs,
                                               const float* __restrict__ wh, const float* __restrict__ bhh) {
    __shared__ float W[Ff][65];
    __shared__ float bias[Ff];
    __shared__ float qr[4][64];
    __shared__ float raw[4][Ff];
    int tid = threadIdx.x;
    for (int i = tid; i < 64 * 64; i += 256) { W[i / 64][i % 64] = we[i]; W[64 + i / 64][i % 64] = ws[i]; }
    for (int i = tid; i < 32 * 64; i += 256) W[128 + i / 64][i % 64] = wh[i];
    for (int i = tid; i < Ff; i += 256) bias[i] = (i < 64) ? be[i] : ((i < 128) ? bs[i - 64] : bhh[i - 128]);
    const float* src = (blockIdx.y == 0) ? g_Q : g_K;
    int tok0 = blockIdx.x * 4;
    for (int i = tid; i < 4 * 64; i += 256) qr[i / 64][i % 64] = src[(size_t)(tok0 + i / 64) * 64 + (i % 64)];
    __syncthreads();
    for (int i = tid; i < 4 * Ff; i += 256) {
        int tt = i / Ff, j = i % Ff;
        float s = bias[j];
#pragma unroll 8
        for (int c = 0; c < 64; c++) s += qr[tt][c] * W[j][c];
        raw[tt][j] = s;
    }
    __syncthreads();
    int w = tid >> 5, lane = tid & 31;
    if (w < 4) {
        int tt = w;
        float an = 0.f, sn = 0.f, un = 0.f;
        for (int j = lane; j < 64; j += 32) { float v = raw[tt][j]; an += v * v; }
        for (int j = 64 + lane; j < 128; j += 32) { float v = raw[tt][j]; sn += v * v; }
        {
            int j = 128 + lane;
            float th = tanhf(raw[tt][j]);
            raw[tt][j] = th;
            un += th * th;
        }
#pragma unroll
        for (int o = 16; o; o >>= 1) {
            an += __shfl_xor_sync(0xffffffffu, an, o);
            sn += __shfl_xor_sync(0xffffffffu, sn, o);
            un += __shfl_xor_sync(0xffffffffu, un, o);
        }
        float inv = 1.f / fmaxf(sqrtf(sn), 1e-12f);
        __syncwarp();
        float* Fdst = (blockIdx.y == 0) ? g_FQ : g_FK;
        int tok = tok0 + tt;
        for (int j = lane; j < Ff; j += 32) {
            float v = raw[tt][j];
            if (j >= 64 && j < 128) v *= inv;
            Fdst[(size_t)tok * Ff + j] = v;
        }
        if (lane == 0) {
            if (blockIdx.y == 0) { g_QA[tok] = an; g_QU[tok] = un; }
            else                 { g_KB[tok] = an; g_KV[tok] = un; }
        }
    }
}

// ============================================================
// K3: score GEMM 128x64 tile, 8x4 micro, 3 groups + fast epilogue
// ============================================================
__global__ __launch_bounds__(256) void k_score(const float* __restrict__ alpha,
                                               const float* __restrict__ beta,
                                               const float* __restrict__ gamma,
                                               const float* __restrict__ temp) {
    __shared__ float As[2][16][LDA];
    __shared__ float Bs[2][16][LDB];
    __shared__ float sAN[128], sUN[128], sBN[64], sVN[64];
    int tid = threadIdx.x;
    int ty = tid >> 4, tx = tid & 15;
    int srow = tid >> 1, sq = (tid & 1) * 2;      // A staging
    int brow = tid >> 2, bq = tid & 3;            // B staging (64 rows x 4 quarters)
    int bh = blockIdx.z;
    int row0 = blockIdx.y * 128, col0 = blockIdx.x * 64;
    const float* Ap = g_FQ + ((size_t)bh * Nn + row0 + srow) * Ff + sq * 4;
    const float* Bp = g_FK + ((size_t)bh * Nn + col0 + brow) * Ff + bq * 4;
    if (tid < 128) { sAN[tid] = g_QA[bh * Nn + row0 + tid]; sUN[tid] = g_QU[bh * Nn + row0 + tid]; }
    else { int t = tid - 128; if (t < 64) { sBN[t] = g_KB[bh * Nn + col0 + t]; sVN[t] = g_KV[bh * Nn + col0 + t]; } }

    u64 aE[8][2] = {}, aS[8][2] = {}, aH[8][2] = {};
    float4 a0v, a1v, bv;

#define S_LDG(KT) \
    a0v = *(const float4*)(Ap + (KT) * 16);     a1v = *(const float4*)(Ap + (KT) * 16 + 4); \
    bv  = *(const float4*)(Bp + (KT) * 16);
#define S_STS(BUF) \
    As[BUF][sq*4+0][srow]=a0v.x; As[BUF][sq*4+1][srow]=a0v.y; As[BUF][sq*4+2][srow]=a0v.z; As[BUF][sq*4+3][srow]=a0v.w; \
    As[BUF][sq*4+4][srow]=a1v.x; As[BUF][sq*4+5][srow]=a1v.y; As[BUF][sq*4+6][srow]=a1v.z; As[BUF][sq*4+7][srow]=a1v.w; \
    Bs[BUF][bq*4+0][brow]=bv.x;  Bs[BUF][bq*4+1][brow]=bv.y;  Bs[BUF][bq*4+2][brow]=bv.z;  Bs[BUF][bq*4+3][brow]=bv.w;
#define S_COMP(BUF, ACC2) \
    _Pragma("unroll") \
    for (int kk = 0; kk < 16; kk++) { \
        float4 a0 = *(const float4*)&As[BUF][kk][ty * 8]; \
        float4 a1 = *(const float4*)&As[BUF][kk][ty * 8 + 4]; \
        float4 b  = *(const float4*)&Bs[BUF][kk][tx * 4]; \
        MICRO8X4(ACC2, a0, a1, b) \
    }
#define S_PAIR(KT, ACC2, LAST) \
    S_LDG(KT + 1) \
    S_COMP(0, ACC2) \
    S_STS(1) \
    __syncthreads(); \
    if (!(LAST)) { S_LDG(KT + 2) } \
    S_COMP(1, ACC2) \
    if (!(LAST)) { S_STS(0) } \
    __syncthreads();

    S_LDG(0) S_STS(0)
    __syncthreads();
    S_PAIR(0, aE, false)
    S_PAIR(2, aE, false)
    S_PAIR(4, aS, false)
    S_PAIR(6, aS, false)
    // chunks 8,9 -> H
    S_LDG(9)
    S_COMP(0, aH)
    S_STS(1)
    __syncthreads();
    S_COMP(1, aH)

    float accE[8][4], accS[8][4], accH[8][4];
#pragma unroll
    for (int i = 0; i < 8; i++) {
        unpack2(aE[i][0], accE[i][0], accE[i][1]); unpack2(aE[i][1], accE[i][2], accE[i][3]);
        unpack2(aS[i][0], accS[i][0], accS[i][1]); unpack2(aS[i][1], accS[i][2], accS[i][3]);
        unpack2(aH[i][0], accH[i][0], accH[i][1]); unpack2(aH[i][1], accH[i][2], accH[i][3]);
    }

    float cE = softplusf(alpha[0]);
    float cS = softplusf(beta[0]);
    float cH = softplusf(gamma[0]);
    float negInvT = -1.f / softplusf(temp[0]);
    float* Sbase = g_S + (size_t)bh * Nn * Nn;
#pragma unroll
    for (int i = 0; i < 8; i++) {
        int rl = ty * 8 + i;
        float an = sAN[rl], un = sUN[rl];
        float one_m_un = 1.f - un;
        float4 o;
        float* op = (float*)&o;
#pragma unroll
        for (int j = 0; j < 4; j++) {
            int cl = tx * 4 + j;
            float bn = sBN[cl], vn = sVN[cl];
            float dE = fast_sqrt(fmaxf(an + bn - 2.f * accE[i][j], 1e-12f));
            float x = fminf(fmaxf(accS[i][j], -1.f + 1e-6f), 1.f - 1e-6f);
            float ax = fabsf(x);
            float poly = fmaf(ax, fmaf(ax, fmaf(ax, -0.0187293f, 0.0742610f), -0.2121144f), 1.5707288f);
            float rr = fast_sqrt(1.f - ax) * poly;
            float dS = (x >= 0.f) ? rr : (3.14159265358979f - rr);
            float dns = fmaxf(un + vn - 2.f * accH[i][j], 0.f);
            float denom = one_m_un * (1.f - vn) + 1e-8f;
            float t = fmaxf(2.f * dns * fast_rcp(denom), 1e-6f);
            float sh = fast_sqrt(t * (t + 2.f));
            float dHp = __logf(1.f + t + sh);
            op[j] = negInvT * (cE * dE + cS * dS + cH * dHp);
        }
        *(float4*)&Sbase[(size_t)(row0 + rl) * Nn + col0 + tx * 4] = o;
    }
}

// ============================================================
// K4: row softmax in place over g_S (unchanged)
// ============================================================
__global__ __launch_bounds__(256) void k_softmax() {
    __shared__ float red[8];
    size_t base = (size_t)blockIdx.x * Nn;
    int tid = threadIdx.x;
    float v[4];
#pragma unroll
    for (int i = 0; i < 4; i++) v[i] = g_S[base + tid + 256 * i];
    float m = fmaxf(fmaxf(v[0], v[1]), fmaxf(v[2], v[3]));
#pragma unroll
    for (int o = 16; o; o >>= 1) m = fmaxf(m, __shfl_xor_sync(0xffffffffu, m, o));
    if ((tid & 31) == 0) red[tid >> 5] = m;
    __syncthreads();
    float M = red[0];
#pragma unroll
    for (int i = 1; i < 8; i++) M = fmaxf(M, red[i]);
    float s = 0.f;
#pragma unroll
    for (int i = 0; i < 4; i++) { v[i] = __expf(v[i] - M); s += v[i]; }
#pragma unroll
    for (int o = 16; o; o >>= 1) s += __shfl_xor_sync(0xffffffffu, s, o);
    __syncthreads();
    if ((tid & 31) == 0) red[tid >> 5] = s;
    __syncthreads();
    float S = 0.f;
#pragma unroll
    for (int i = 0; i < 8; i++) S += red[i];
    float inv = 1.f / S;
#pragma unroll
    for (int i = 0; i < 4; i++) g_S[base + tid + 256 * i] = v[i] * inv;
}

// ============================================================
// K5: attn @ V. 128x64 tile, 8x4 micro.
// ============================================================
__global__ __launch_bounds__(256) void k_av() {
    __shared__ float As[2][16][LDA];
    __shared__ float Bs[2][16][LDB];
    int tid = threadIdx.x;
    int ty = tid >> 4, tx = tid & 15;
    int srow = tid >> 1, sq = (tid & 1) * 2;    // A staging
    int vkrow = tid >> 4, vq = tid & 15;        // V staging: 16 k-rows x 16 float4
    int bh = blockIdx.y;
    int row0 = blockIdx.x * 128;
    const float* Ap = g_S + (size_t)bh * Nn * Nn + (size_t)(row0 + srow) * Nn + sq * 4;
    const float* Vbase = g_V + (size_t)bh * Nn * DH;
    u64 acc2[8][2] = {};
    float4 a0v, a1v, bv;

#define AV_LDG(KT) \
    a0v = *(const float4*)(Ap + (KT) * 16);     a1v = *(const float4*)(Ap + (KT) * 16 + 4); \
    bv  = *(const float4*)(Vbase + (size_t)((KT) * 16 + vkrow) * DH + vq * 4);
#define AV_STS(BUF) \
    As[BUF][sq*4+0][srow]=a0v.x; As[BUF][sq*4+1][srow]=a0v.y; As[BUF][sq*4+2][srow]=a0v.z; As[BUF][sq*4+3][srow]=a0v.w; \
    As[BUF][sq*4+4][srow]=a1v.x; As[BUF][sq*4+5][srow]=a1v.y; As[BUF][sq*4+6][srow]=a1v.z; As[BUF][sq*4+7][srow]=a1v.w; \
    *(float4*)&Bs[BUF][vkrow][vq * 4] = bv;
#define AV_COMP(BUF) \
    _Pragma("unroll") \
    for (int kk = 0; kk < 16; kk++) { \
        float4 a0 = *(const float4*)&As[BUF][kk][ty * 8]; \
        float4 a1 = *(const float4*)&As[BUF][kk][ty * 8 + 4]; \
        float4 b  = *(const float4*)&Bs[BUF][kk][tx * 4]; \
        MICRO8X4(acc2, a0, a1, b) \
    }

    AV_LDG(0) AV_STS(0)
    __syncthreads();
    for (int kt = 0; kt < 64; kt += 2) {
        if (kt + 1 < 64) { AV_LDG(kt + 1) }
        AV_COMP(0)
        if (kt + 1 < 64) { AV_STS(1) }
        __syncthreads();
        if (kt + 1 < 64) {
            if (kt + 2 < 64) { AV_LDG(kt + 2) }
            AV_COMP(1)
            if (kt + 2 < 64) { AV_STS(0) }
            __syncthreads();
        }
    }

    int b = bh / Hh, h = bh % Hh;
#pragma unroll
    for (int i = 0; i < 8; i++) {
        float4 o;
        unpack2(acc2[i][0], o.x, o.y);
        unpack2(acc2[i][1], o.z, o.w);
        int tok = row0 + ty * 8 + i;
        *(float4*)&g_O[((size_t)(b * Nn + tok)) * INNER + h * DH + tx * 4] = o;
    }
}

// ============================================================
// K6: final projection. 128x128 tile, 8x8 micro.
// ============================================================
__global__ __launch_bounds__(256) void k_proj(const float* __restrict__ wp,
                                              const float* __restrict__ bp,
                                              float* __restrict__ out) {
    __shared__ float As[2][16][LDA];
    __shared__ float Bs[2][16][LDA];
    int tid = threadIdx.x;
    int ty = tid >> 4, tx = tid & 15;
    int srow = tid >> 1, sq = (tid & 1) * 2;
    const float* Ap = g_O + ((size_t)(blockIdx.y * 128) + srow) * INNER + sq * 4;
    const float* Bp = wp + ((size_t)(blockIdx.x * 128) + srow) * INNER + sq * 4;
    u64 acc2[8][4] = {};
    float4 a0v, a1v, b0v, b1v;

#define P_LDG(KT) \
    a0v = *(const float4*)(Ap + (KT) * 16);     a1v = *(const float4*)(Ap + (KT) * 16 + 4); \
    b0v = *(const float4*)(Bp + (KT) * 16);     b1v = *(const float4*)(Bp + (KT) * 16 + 4);
#define P_STS(BUF) \
    As[BUF][sq*4+0][srow]=a0v.x; As[BUF][sq*4+1][srow]=a0v.y; As[BUF][sq*4+2][srow]=a0v.z; As[BUF][sq*4+3][srow]=a0v.w; \
    As[BUF][sq*4+4][srow]=a1v.x; As[BUF][sq*4+5][srow]=a1v.y; As[BUF][sq*4+6][srow]=a1v.z; As[BUF][sq*4+7][srow]=a1v.w; \
    Bs[BUF][sq*4+0][srow]=b0v.x; Bs[BUF][sq*4+1][srow]=b0v.y; Bs[BUF][sq*4+2][srow]=b0v.z; Bs[BUF][sq*4+3][srow]=b0v.w; \
    Bs[BUF][sq*4+4][srow]=b1v.x; Bs[BUF][sq*4+5][srow]=b1v.y; Bs[BUF][sq*4+6][srow]=b1v.z; Bs[BUF][sq*4+7][srow]=b1v.w;
#define P_COMP(BUF) \
    _Pragma("unroll") \
    for (int kk = 0; kk < 16; kk++) { \
        float4 a0 = *(const float4*)&As[BUF][kk][ty * 8]; \
        float4 a1 = *(const float4*)&As[BUF][kk][ty * 8 + 4]; \
        float4 b0 = *(const float4*)&Bs[BUF][kk][tx * 8]; \
        float4 b1 = *(const float4*)&Bs[BUF][kk][tx * 8 + 4]; \
        MICRO8X8(acc2, a0, a1, b0, b1) \
    }

    P_LDG(0) P_STS(0)
    __syncthreads();
    for (int kt = 0; kt < 32; kt += 2) {
        if (kt + 1 < 32) { P_LDG(kt + 1) }
        P_COMP(0)
        if (kt + 1 < 32) { P_STS(1) }
        __syncthreads();
        if (kt + 1 < 32) {
            if (kt + 2 < 32) { P_LDG(kt + 2) }
            P_COMP(1)
            if (kt + 2 < 32) { P_STS(0) }
            __syncthreads();
        }
    }

    int m0 = blockIdx.y * 128 + ty * 8;
    int n0 = blockIdx.x * 128 + tx * 8;
    float4 bias0 = *(const float4*)&bp[n0];
    float4 bias1 = *(const float4*)&bp[n0 + 4];
#pragma unroll
    for (int i = 0; i < 8; i++) {
        float4 o0, o1;
        unpack2(acc2[i][0], o0.x, o0.y); unpack2(acc2[i][1], o0.z, o0.w);
        unpack2(acc2[i][2], o1.x, o1.y); unpack2(acc2[i][3], o1.z, o1.w);
        o0.x += bias0.x; o0.y += bias0.y; o0.z += bias0.z; o0.w += bias0.w;
        o1.x += bias1.x; o1.y += bias1.y; o1.z += bias1.z; o1.w += bias1.w;
        *(float4*)&out[(size_t)(m0 + i) * Cc + n0] = o0;
        *(float4*)&out[(size_t)(m0 + i) * Cc + n0 + 4] = o1;
    }
}

extern "C" void kernel_launch(void* const* d_in, const int* in_sizes, int n_in,
                              void* d_out, int out_size) {
    const float* x      = (const float*)d_in[0];
    const float* w_qkv  = (const float*)d_in[1];
    const float* w_proj = (const float*)d_in[2];
    const float* b_proj = (const float*)d_in[3];
    const float* w_e    = (const float*)d_in[4];
    const float* b_e    = (const float*)d_in[5];
    const float* w_s    = (const float*)d_in[6];
    const float* b_s    = (const float*)d_in[7];
    const float* w_h    = (const float*)d_in[8];
    const float* b_h    = (const float*)d_in[9];
    const float* alpha  = (const float*)d_in[10];
    const float* beta   = (const float*)d_in[11];
    const float* gamma  = (const float*)d_in[12];
    const float* temp   = (const float*)d_in[13];
    float* out = (float*)d_out;

    k_qkv<<<dim3(12, 32), 256>>>(x, w_qkv);
    k_embed<<<dim3(BH * Nn / 4, 2), 256>>>(w_e, b_e, w_s, b_s, w_h, b_h);
    k_score<<<dim3(16, 8, BH), 256>>>(alpha, beta, gamma, temp);
    k_softmax<<<BH * Nn, 256>>>();
    k_av<<<dim3(8, BH), 256>>>();
    k_proj<<<dim3(4, 32), 256>>>(w_proj, b_proj, out);
}

// round 9
// speedup vs baseline: 1.0296x; 1.0296x over previous
#include <cuda_runtime.h>
#include <cuda_bf16.h>
#include <math.h>
#include <stdint.h>

#define Bsz 4
#define Nn 1024
#define Cc 512
#define Hh 8
#define DH 64
#define BH 32
#define INNER 512
#define Ff 160   // 64 (E) + 64 (S) + 32 (H)
#define LDA 132  // smem stride for 128-wide tiles (k_qkv / k_proj)

typedef unsigned long long u64;

// ---- scratch (static device allocations; no runtime alloc) ----
__device__ float g_Q[BH * Nn * DH];
__device__ float g_K[BH * Nn * DH];
__device__ float g_V[BH * Nn * DH];
__device__ float g_FQ[BH * Nn * Ff];
__device__ float g_FK[BH * Nn * Ff];
__device__ float g_QA[BH * Nn];
__device__ float g_QU[BH * Nn];
__device__ float g_KB[BH * Nn];
__device__ float g_KV[BH * Nn];
__device__ float g_O[Bsz * Nn * INNER];

__device__ __forceinline__ float softplusf(float x) {
    return (x > 20.f) ? x : log1pf(expf(x));
}
__device__ __forceinline__ float fast_sqrt(float x) {
    float r; asm("sqrt.approx.f32 %0, %1;" : "=f"(r) : "f"(x)); return r;
}
__device__ __forceinline__ float fast_rcp(float x) {
    float r; asm("rcp.approx.f32 %0, %1;" : "=f"(r) : "f"(x)); return r;
}

// ---- packed f32x2 FMA (kept for k_qkv/k_proj; semantics = 2x exact FMA) ----
__device__ __forceinline__ void fma2(u64& d, u64 a, u64 b) {
    asm("fma.rn.f32x2 %0, %1, %2, %0;" : "+l"(d) : "l"(a), "l"(b));
}
__device__ __forceinline__ u64 pack2(float lo, float hi) {
    u64 r; asm("mov.b64 %0, {%1, %2};" : "=l"(r) : "f"(lo), "f"(hi)); return r;
}
__device__ __forceinline__ void unpack2(u64 v, float& lo, float& hi) {
    asm("mov.b64 {%0, %1}, %2;" : "=f"(lo), "=f"(hi) : "l"(v));
}

#define MICRO8X8(ACC2, a0, a1, b0, b1) {                                      \
    u64 q0 = pack2(b0.x, b0.y), q1 = pack2(b0.z, b0.w);                       \
    u64 q2 = pack2(b1.x, b1.y), q3 = pack2(b1.z, b1.w);                       \
    u64 ar;                                                                   \
    ar = pack2(a0.x, a0.x); fma2(ACC2[0][0],ar,q0); fma2(ACC2[0][1],ar,q1); fma2(ACC2[0][2],ar,q2); fma2(ACC2[0][3],ar,q3); \
    ar = pack2(a0.y, a0.y); fma2(ACC2[1][0],ar,q0); fma2(ACC2[1][1],ar,q1); fma2(ACC2[1][2],ar,q2); fma2(ACC2[1][3],ar,q3); \
    ar = pack2(a0.z, a0.z); fma2(ACC2[2][0],ar,q0); fma2(ACC2[2][1],ar,q1); fma2(ACC2[2][2],ar,q2); fma2(ACC2[2][3],ar,q3); \
    ar = pack2(a0.w, a0.w); fma2(ACC2[3][0],ar,q0); fma2(ACC2[3][1],ar,q1); fma2(ACC2[3][2],ar,q2); fma2(ACC2[3][3],ar,q3); \
    ar = pack2(a1.x, a1.x); fma2(ACC2[4][0],ar,q0); fma2(ACC2[4][1],ar,q1); fma2(ACC2[4][2],ar,q2); fma2(ACC2[4][3],ar,q3); \
    ar = pack2(a1.y, a1.y); fma2(ACC2[5][0],ar,q0); fma2(ACC2[5][1],ar,q1); fma2(ACC2[5][2],ar,q2); fma2(ACC2[5][3],ar,q3); \
    ar = pack2(a1.z, a1.z); fma2(ACC2[6][0],ar,q0); fma2(ACC2[6][1],ar,q1); fma2(ACC2[6][2],ar,q2); fma2(ACC2[6][3],ar,q3); \
    ar = pack2(a1.w, a1.w); fma2(ACC2[7][0],ar,q0); fma2(ACC2[7][1],ar,q1); fma2(ACC2[7][2],ar,q2); fma2(ACC2[7][3],ar,q3); \
}

// ============================================================
// K1: qkv = x @ w_qkv^T -> per-head Q/K/V. 128x128 tile, 8x8 micro.
// ============================================================
__global__ __launch_bounds__(256) void k_qkv(const float* __restrict__ x,
                                             const float* __restrict__ w) {
    __shared__ float As[2][16][LDA];
    __shared__ float Bs[2][16][LDA];
    int tid = threadIdx.x;
    int ty = tid >> 4, tx = tid & 15;
    int srow = tid >> 1, sq = (tid & 1) * 2;
    const float* Ap = x + ((size_t)(blockIdx.y * 128) + srow) * Cc + sq * 4;
    const float* Bp = w + ((size_t)(blockIdx.x * 128) + srow) * Cc + sq * 4;
    u64 acc2[8][4] = {};
    float4 a0v, a1v, b0v, b1v;

#define Q_LDG(KT) \
    a0v = *(const float4*)(Ap + (KT) * 16);     a1v = *(const float4*)(Ap + (KT) * 16 + 4); \
    b0v = *(const float4*)(Bp + (KT) * 16);     b1v = *(const float4*)(Bp + (KT) * 16 + 4);
#define Q_STS(BUF) \
    As[BUF][sq*4+0][srow]=a0v.x; As[BUF][sq*4+1][srow]=a0v.y; As[BUF][sq*4+2][srow]=a0v.z; As[BUF][sq*4+3][srow]=a0v.w; \
    As[BUF][sq*4+4][srow]=a1v.x; As[BUF][sq*4+5][srow]=a1v.y; As[BUF][sq*4+6][srow]=a1v.z; As[BUF][sq*4+7][srow]=a1v.w; \
    Bs[BUF][sq*4+0][srow]=b0v.x; Bs[BUF][sq*4+1][srow]=b0v.y; Bs[BUF][sq*4+2][srow]=b0v.z; Bs[BUF][sq*4+3][srow]=b0v.w; \
    Bs[BUF][sq*4+4][srow]=b1v.x; Bs[BUF][sq*4+5][srow]=b1v.y; Bs[BUF][sq*4+6][srow]=b1v.z; Bs[BUF][sq*4+7][srow]=b1v.w;
#define Q_COMP(BUF) \
    _Pragma("unroll") \
    for (int kk = 0; kk < 16; kk++) { \
        float4 a0 = *(const float4*)&As[BUF][kk][ty * 8]; \
        float4 a1 = *(const float4*)&As[BUF][kk][ty * 8 + 4]; \
        float4 b0 = *(const float4*)&Bs[BUF][kk][tx * 8]; \
        float4 b1 = *(const float4*)&Bs[BUF][kk][tx * 8 + 4]; \
        MICRO8X8(acc2, a0, a1, b0, b1) \
    }

    Q_LDG(0) Q_STS(0)
    __syncthreads();
    for (int kt = 0; kt < 32; kt += 2) {
        if (kt + 1 < 32) { Q_LDG(kt + 1) }
        Q_COMP(0)
        if (kt + 1 < 32) { Q_STS(1) }
        __syncthreads();
        if (kt + 1 < 32) {
            if (kt + 2 < 32) { Q_LDG(kt + 2) }
            Q_COMP(1)
            if (kt + 2 < 32) { Q_STS(0) }
            __syncthreads();
        }
    }

    float acc[8][8];
#pragma unroll
    for (int i = 0; i < 8; i++)
#pragma unroll
        for (int p = 0; p < 4; p++) unpack2(acc2[i][p], acc[i][2 * p], acc[i][2 * p + 1]);

    int m0 = blockIdx.y * 128 + ty * 8;
    int n0 = blockIdx.x * 128 + tx * 8;
#pragma unroll
    for (int i = 0; i < 8; i++) {
        int m = m0 + i;
        int b = m / Nn, n = m % Nn;
#pragma unroll
        for (int j = 0; j < 8; j++) {
            int jc = n0 + j;
            int part = jc / INNER, r = jc % INNER;
            int h = r / DH, d = r % DH;
            float* dst = (part == 0) ? g_Q : ((part == 1) ? g_K : g_V);
            dst[((size_t)(b * Hh + h) * Nn + n) * DH + d] = acc[i][j];
        }
    }
}

// ============================================================
// K2: per-token metric embeddings (unchanged)
// ============================================================
__global__ __launch_bounds__(256) void k_embed(const float* __restrict__ we, const float* __restrict__ be,
                                               const float* __restrict__ ws, const float* __restrict__ bs,
                                               const float* __restrict__ wh, const float* __restrict__ bhh) {
    __shared__ float W[Ff][65];
    __shared__ float bias[Ff];
    __shared__ float qr[4][64];
    __shared__ float raw[4][Ff];
    int tid = threadIdx.x;
    for (int i = tid; i < 64 * 64; i += 256) { W[i / 64][i % 64] = we[i]; W[64 + i / 64][i % 64] = ws[i]; }
    for (int i = tid; i < 32 * 64; i += 256) W[128 + i / 64][i % 64] = wh[i];
    for (int i = tid; i < Ff; i += 256) bias[i] = (i < 64) ? be[i] : ((i < 128) ? bs[i - 64] : bhh[i - 128]);
    const float* src = (blockIdx.y == 0) ? g_Q : g_K;
    int tok0 = blockIdx.x * 4;
    for (int i = tid; i < 4 * 64; i += 256) qr[i / 64][i % 64] = src[(size_t)(tok0 + i / 64) * 64 + (i % 64)];
    __syncthreads();
    for (int i = tid; i < 4 * Ff; i += 256) {
        int tt = i / Ff, j = i % Ff;
        float s = bias[j];
#pragma unroll 8
        for (int c = 0; c < 64; c++) s += qr[tt][c] * W[j][c];
        raw[tt][j] = s;
    }
    __syncthreads();
    int w = tid >> 5, lane = tid & 31;
    if (w < 4) {
        int tt = w;
        float an = 0.f, sn = 0.f, un = 0.f;
        for (int j = lane; j < 64; j += 32) { float v = raw[tt][j]; an += v * v; }
        for (int j = 64 + lane; j < 128; j += 32) { float v = raw[tt][j]; sn += v * v; }
        {
            int j = 128 + lane;
            float th = tanhf(raw[tt][j]);
            raw[tt][j] = th;
            un += th * th;
        }
#pragma unroll
        for (int o = 16; o; o >>= 1) {
            an += __shfl_xor_sync(0xffffffffu, an, o);
            sn += __shfl_xor_sync(0xffffffffu, sn, o);
            un += __shfl_xor_sync(0xffffffffu, un, o);
        }
        float inv = 1.f / fmaxf(sqrtf(sn), 1e-12f);
        __syncwarp();
        float* Fdst = (blockIdx.y == 0) ? g_FQ : g_FK;
        int tok = tok0 + tt;
        for (int j = lane; j < Ff; j += 32) {
            float v = raw[tt][j];
            if (j >= 64 && j < 128) v *= inv;
            Fdst[(size_t)tok * Ff + j] = v;
        }
        if (lane == 0) {
            if (blockIdx.y == 0) { g_QA[tok] = an; g_QU[tok] = un; }
            else                 { g_KB[tok] = an; g_KV[tok] = un; }
        }
    }
}

// ============================================================
// K3: FUSED attention: score GEMM (staged groups) + online softmax + P@V
// q-tile 64 rows, k-tiles of 64 cols, 16x16 threads, 4x4 micro.
// ============================================================
// dynamic smem layout (float offsets)
#define O_ARES 0        // 160 x 68  (q features transposed [k][row])
#define O_BS   10880    // 2 x 16 x 68 (k-feature chunks, [k][row])
#define O_PS   13056    // 64 x 68  (P tile [row][c])
#define O_VS   17408    // 64 x 68  (V tile [c][d])
#define O_AN   21760
#define O_UN   21824
#define O_BN   21888
#define O_VN   21952
#define ATT_SMEM_BYTES (22016 * 4)

#define FMA16(ACC, a, b) \
    ACC[0][0] += a.x * b.x; ACC[0][1] += a.x * b.y; ACC[0][2] += a.x * b.z; ACC[0][3] += a.x * b.w; \
    ACC[1][0] += a.y * b.x; ACC[1][1] += a.y * b.y; ACC[1][2] += a.y * b.z; ACC[1][3] += a.y * b.w; \
    ACC[2][0] += a.z * b.x; ACC[2][1] += a.z * b.y; ACC[2][2] += a.z * b.z; ACC[2][3] += a.z * b.w; \
    ACC[3][0] += a.w * b.x; ACC[3][1] += a.w * b.y; ACC[3][2] += a.w * b.z; ACC[3][3] += a.w * b.w;

#define G2STEP(E, VB) { \
    accO[0][0]+=pa0.E*VB.x; accO[0][1]+=pa0.E*VB.y; accO[0][2]+=pa0.E*VB.z; accO[0][3]+=pa0.E*VB.w; \
    accO[1][0]+=pa1.E*VB.x; accO[1][1]+=pa1.E*VB.y; accO[1][2]+=pa1.E*VB.z; accO[1][3]+=pa1.E*VB.w; \
    accO[2][0]+=pa2.E*VB.x; accO[2][1]+=pa2.E*VB.y; accO[2][2]+=pa2.E*VB.z; accO[2][3]+=pa2.E*VB.w; \
    accO[3][0]+=pa3.E*VB.x; accO[3][1]+=pa3.E*VB.y; accO[3][2]+=pa3.E*VB.z; accO[3][3]+=pa3.E*VB.w; }

__global__ __launch_bounds__(256, 2) void k_attn(const float* __restrict__ alpha,
                                                 const float* __restrict__ beta,
                                                 const float* __restrict__ gamma,
                                                 const float* __restrict__ temp) {
    extern __shared__ float sm[];
    int tid = threadIdx.x;
    int ty = tid >> 4, tx = tid & 15;
    int brow = tid >> 2, bq = tid & 3;
    int bh = blockIdx.y;
    int row0 = blockIdx.x * 64;

    const float* FQb = g_FQ + ((size_t)bh * Nn + row0) * Ff;
    const float* FKb = g_FK + (size_t)bh * Nn * Ff;
    const float* Vb  = g_V + (size_t)bh * Nn * DH;

    // one-time: load q-feature tile transposed into resident smem + q norms
#pragma unroll
    for (int t = 0; t < 10; t++) {
        int idx = tid + 256 * t;            // 2560 float4s
        int r = idx / 40, q4 = idx % 40;
        float4 v = *(const float4*)(FQb + (size_t)r * Ff + q4 * 4);
        sm[O_ARES + (q4 * 4 + 0) * 68 + r] = v.x;
        sm[O_ARES + (q4 * 4 + 1) * 68 + r] = v.y;
        sm[O_ARES + (q4 * 4 + 2) * 68 + r] = v.z;
        sm[O_ARES + (q4 * 4 + 3) * 68 + r] = v.w;
    }
    if (tid < 64) {
        sm[O_AN + tid] = g_QA[bh * Nn + row0 + tid];
        sm[O_UN + tid] = g_QU[bh * Nn + row0 + tid];
    }

    float cE = softplusf(alpha[0]);
    float cS = softplusf(beta[0]);
    float cH = softplusf(gamma[0]);
    float negInvT = -1.f / softplusf(temp[0]);

    float m_[4], l_[4], accO[4][4];
#pragma unroll
    for (int i = 0; i < 4; i++) {
        m_[i] = -1e30f; l_[i] = 0.f;
#pragma unroll
        for (int j = 0; j < 4; j++) accO[i][j] = 0.f;
    }
    __syncthreads();

    for (int kt = 0; kt < 16; kt++) {
        int col0 = kt * 64;
        const float* Bp = FKb + (size_t)(col0 + brow) * Ff + bq * 4;

        // prologue: stage B chunk 0 + k norms
        {
            float4 v = *(const float4*)(Bp);
            sm[O_BS + (bq * 4 + 0) * 68 + brow] = v.x;
            sm[O_BS + (bq * 4 + 1) * 68 + brow] = v.y;
            sm[O_BS + (bq * 4 + 2) * 68 + brow] = v.z;
            sm[O_BS + (bq * 4 + 3) * 68 + brow] = v.w;
        }
        if (tid < 64) {
            sm[O_BN + tid] = g_KB[bh * Nn + col0 + tid];
            sm[O_VN + tid] = g_KV[bh * Nn + col0 + tid];
        }
        __syncthreads();

        float acc[4][4] = {};
        float s_[4][4];
        float4 bvreg;

#pragma unroll
        for (int c = 0; c < 10; c++) {
            if (c < 9) bvreg = *(const float4*)(Bp + (c + 1) * 16);
            int bb = O_BS + (c & 1) * 1088;
#pragma unroll
            for (int kk = 0; kk < 16; kk++) {
                float4 a = *(const float4*)&sm[O_ARES + (c * 16 + kk) * 68 + ty * 4];
                float4 b = *(const float4*)&sm[bb + kk * 68 + tx * 4];
                FMA16(acc, a, b)
            }
            if (c < 9) {
                int b2 = O_BS + ((c + 1) & 1) * 1088;
                sm[b2 + (bq * 4 + 0) * 68 + brow] = bvreg.x;
                sm[b2 + (bq * 4 + 1) * 68 + brow] = bvreg.y;
                sm[b2 + (bq * 4 + 2) * 68 + brow] = bvreg.z;
                sm[b2 + (bq * 4 + 3) * 68 + brow] = bvreg.w;
            }
            if (c == 3) {        // finalize Euclidean group
#pragma unroll
                for (int i = 0; i < 4; i++) {
                    float an = sm[O_AN + ty * 4 + i];
#pragma unroll
                    for (int j = 0; j < 4; j++) {
                        float bn = sm[O_BN + tx * 4 + j];
                        s_[i][j] = cE * fast_sqrt(fmaxf(an + bn - 2.f * acc[i][j], 1e-12f));
                        acc[i][j] = 0.f;
                    }
                }
            }
            if (c == 7) {        // finalize spherical group
#pragma unroll
                for (int i = 0; i < 4; i++)
#pragma unroll
                    for (int j = 0; j < 4; j++) {
                        float x = fminf(fmaxf(acc[i][j], -1.f + 1e-6f), 1.f - 1e-6f);
                        float ax = fabsf(x);
                        float poly = fmaf(ax, fmaf(ax, fmaf(ax, -0.0187293f, 0.0742610f), -0.2121144f), 1.5707288f);
                        float rr = fast_sqrt(1.f - ax) * poly;
                        float dS = (x >= 0.f) ? rr : (3.14159265358979f - rr);
                        s_[i][j] += cS * dS;
                        acc[i][j] = 0.f;
                    }
            }
            if (c == 9) {        // finalize hyperbolic group + temperature
#pragma unroll
                for (int i = 0; i < 4; i++) {
                    float un = sm[O_UN + ty * 4 + i];
                    float one_m_un = 1.f - un;
#pragma unroll
                    for (int j = 0; j < 4; j++) {
                        float vn = sm[O_VN + tx * 4 + j];
                        float dns = fmaxf(un + vn - 2.f * acc[i][j], 0.f);
                        float denom = one_m_un * (1.f - vn) + 1e-8f;
                        float t = fmaxf(2.f * dns * fast_rcp(denom), 1e-6f);
                        float sh = fast_sqrt(t * (t + 2.f));
                        float dHp = __logf(1.f + t + sh);
                        s_[i][j] = negInvT * (s_[i][j] + cH * dHp);
                    }
                }
            }
            if (c < 9) __syncthreads();
        }

        // prefetch V tile into registers (hidden behind softmax math)
        float4 vr[4];
#pragma unroll
        for (int t = 0; t < 4; t++) {
            int idx = tid + 256 * t;          // 1024 float4s
            int c = idx >> 4, dq = idx & 15;
            vr[t] = *(const float4*)(Vb + (size_t)(col0 + c) * DH + dq * 4);
        }

        // online softmax update + P to smem
#pragma unroll
        for (int i = 0; i < 4; i++) {
            float rm = fmaxf(fmaxf(s_[i][0], s_[i][1]), fmaxf(s_[i][2], s_[i][3]));
#pragma unroll
            for (int o = 1; o < 16; o <<= 1) rm = fmaxf(rm, __shfl_xor_sync(0xffffffffu, rm, o));
            float mn = fmaxf(m_[i], rm);
            float sc = __expf(m_[i] - mn);
            float p0 = __expf(s_[i][0] - mn);
            float p1 = __expf(s_[i][1] - mn);
            float p2 = __expf(s_[i][2] - mn);
            float p3 = __expf(s_[i][3] - mn);
            float rs = (p0 + p1) + (p2 + p3);
#pragma unroll
            for (int o = 1; o < 16; o <<= 1) rs += __shfl_xor_sync(0xffffffffu, rs, o);
            l_[i] = l_[i] * sc + rs;
            m_[i] = mn;
            accO[i][0] *= sc; accO[i][1] *= sc; accO[i][2] *= sc; accO[i][3] *= sc;
            *(float4*)&sm[O_PS + (ty * 4 + i) * 68 + tx * 4] = make_float4(p0, p1, p2, p3);
        }
        // store V tile
#pragma unroll
        for (int t = 0; t < 4; t++) {
            int idx = tid + 256 * t;
            int c = idx >> 4, dq = idx & 15;
            *(float4*)&sm[O_VS + c * 68 + dq * 4] = vr[t];
        }
        __syncthreads();

        // P @ V accumulation
#pragma unroll
        for (int c4 = 0; c4 < 16; c4++) {
            float4 pa0 = *(const float4*)&sm[O_PS + (ty * 4 + 0) * 68 + c4 * 4];
            float4 pa1 = *(const float4*)&sm[O_PS + (ty * 4 + 1) * 68 + c4 * 4];
            float4 pa2 = *(const float4*)&sm[O_PS + (ty * 4 + 2) * 68 + c4 * 4];
            float4 pa3 = *(const float4*)&sm[O_PS + (ty * 4 + 3) * 68 + c4 * 4];
            float4 vb0 = *(const float4*)&sm[O_VS + (c4 * 4 + 0) * 68 + tx * 4];
            float4 vb1 = *(const float4*)&sm[O_VS + (c4 * 4 + 1) * 68 + tx * 4];
            float4 vb2 = *(const float4*)&sm[O_VS + (c4 * 4 + 2) * 68 + tx * 4];
            float4 vb3 = *(const float4*)&sm[O_VS + (c4 * 4 + 3) * 68 + tx * 4];
            G2STEP(x, vb0)
            G2STEP(y, vb1)
            G2STEP(z, vb2)
            G2STEP(w, vb3)
        }
        __syncthreads();
    }

    // normalize + write O
    int b = bh / Hh, h = bh % Hh;
#pragma unroll
    for (int i = 0; i < 4; i++) {
        float inv = fast_rcp(l_[i]);
        float4 o = make_float4(accO[i][0] * inv, accO[i][1] * inv,
                               accO[i][2] * inv, accO[i][3] * inv);
        *(float4*)&g_O[((size_t)(b * Nn + row0 + ty * 4 + i)) * INNER + h * DH + tx * 4] = o;
    }
}

// ============================================================
// K6: final projection. 128x128 tile, 8x8 micro.
// ============================================================
__global__ __launch_bounds__(256) void k_proj(const float* __restrict__ wp,
                                              const float* __restrict__ bp,
                                              float* __restrict__ out) {
    __shared__ float As[2][16][LDA];
    __shared__ float Bs[2][16][LDA];
    int tid = threadIdx.x;
    int ty = tid >> 4, tx = tid & 15;
    int srow = tid >> 1, sq = (tid & 1) * 2;
    const float* Ap = g_O + ((size_t)(blockIdx.y * 128) + srow) * INNER + sq * 4;
    const float* Bp = wp + ((size_t)(blockIdx.x * 128) + srow) * INNER + sq * 4;
    u64 acc2[8][4] = {};
    float4 a0v, a1v, b0v, b1v;

#define P_LDG(KT) \
    a0v = *(const float4*)(Ap + (KT) * 16);     a1v = *(const float4*)(Ap + (KT) * 16 + 4); \
    b0v = *(const float4*)(Bp + (KT) * 16);     b1v = *(const float4*)(Bp + (KT) * 16 + 4);
#define P_STS(BUF) \
    As[BUF][sq*4+0][srow]=a0v.x; As[BUF][sq*4+1][srow]=a0v.y; As[BUF][sq*4+2][srow]=a0v.z; As[BUF][sq*4+3][srow]=a0v.w; \
    As[BUF][sq*4+4][srow]=a1v.x; As[BUF][sq*4+5][srow]=a1v.y; As[BUF][sq*4+6][srow]=a1v.z; As[BUF][sq*4+7][srow]=a1v.w; \
    Bs[BUF][sq*4+0][srow]=b0v.x; Bs[BUF][sq*4+1][srow]=b0v.y; Bs[BUF][sq*4+2][srow]=b0v.z; Bs[BUF][sq*4+3][srow]=b0v.w; \
    Bs[BUF][sq*4+4][srow]=b1v.x; Bs[BUF][sq*4+5][srow]=b1v.y; Bs[BUF][sq*4+6][srow]=b1v.z; Bs[BUF][sq*4+7][srow]=b1v.w;
#define P_COMP(BUF) \
    _Pragma("unroll") \
    for (int kk = 0; kk < 16; kk++) { \
        float4 a0 = *(const float4*)&As[BUF][kk][ty * 8]; \
        float4 a1 = *(const float4*)&As[BUF][kk][ty * 8 + 4]; \
        float4 b0 = *(const float4*)&Bs[BUF][kk][tx * 8]; \
        float4 b1 = *(const float4*)&Bs[BUF][kk][tx * 8 + 4]; \
        MICRO8X8(acc2, a0, a1, b0, b1) \
    }

    P_LDG(0) P_STS(0)
    __syncthreads();
    for (int kt = 0; kt < 32; kt += 2) {
        if (kt + 1 < 32) { P_LDG(kt + 1) }
        P_COMP(0)
        if (kt + 1 < 32) { P_STS(1) }
        __syncthreads();
        if (kt + 1 < 32) {
            if (kt + 2 < 32) { P_LDG(kt + 2) }
            P_COMP(1)
            if (kt + 2 < 32) { P_STS(0) }
            __syncthreads();
        }
    }

    int m0 = blockIdx.y * 128 + ty * 8;
    int n0 = blockIdx.x * 128 + tx * 8;
    float4 bias0 = *(const float4*)&bp[n0];
    float4 bias1 = *(const float4*)&bp[n0 + 4];
#pragma unroll
    for (int i = 0; i < 8; i++) {
        float4 o0, o1;
        unpack2(acc2[i][0], o0.x, o0.y); unpack2(acc2[i][1], o0.z, o0.w);
        unpack2(acc2[i][2], o1.x, o1.y); unpack2(acc2[i][3], o1.z, o1.w);
        o0.x += bias0.x; o0.y += bias0.y; o0.z += bias0.z; o0.w += bias0.w;
        o1.x += bias1.x; o1.y += bias1.y; o1.z += bias1.z; o1.w += bias1.w;
        *(float4*)&out[(size_t)(m0 + i) * Cc + n0] = o0;
        *(float4*)&out[(size_t)(m0 + i) * Cc + n0 + 4] = o1;
    }
}

extern "C" void kernel_launch(void* const* d_in, const int* in_sizes, int n_in,
                              void* d_out, int out_size) {
    const float* x      = (const float*)d_in[0];
    const float* w_qkv  = (const float*)d_in[1];
    const float* w_proj = (const float*)d_in[2];
    const float* b_proj = (const float*)d_in[3];
    const float* w_e    = (const float*)d_in[4];
    const float* b_e    = (const float*)d_in[5];
    const float* w_s    = (const float*)d_in[6];
    const float* b_s    = (const float*)d_in[7];
    const float* w_h    = (const float*)d_in[8];
    const float* b_h    = (const float*)d_in[9];
    const float* alpha  = (const float*)d_in[10];
    const float* beta   = (const float*)d_in[11];
    const float* gamma  = (const float*)d_in[12];
    const float* temp   = (const float*)d_in[13];
    float* out = (float*)d_out;

    cudaFuncSetAttribute(k_attn, cudaFuncAttributeMaxDynamicSharedMemorySize, ATT_SMEM_BYTES);

    k_qkv<<<dim3(12, 32), 256>>>(x, w_qkv);
    k_embed<<<dim3(BH * Nn / 4, 2), 256>>>(w_e, b_e, w_s, b_s, w_h, b_h);
    k_attn<<<dim3(16, BH), 256, ATT_SMEM_BYTES>>>(alpha, beta, gamma, temp);
    k_proj<<<dim3(4, 32), 256>>>(w_proj, b_proj, out);
}